// round 1
// baseline (speedup 1.0000x reference)
#include <cuda_runtime.h>

#define W0 0.23037781330885523f
#define W1 0.7148465705525415f
#define W2 0.6308807679295904f
#define W3 (-0.02798376941698385f)
#define W4 (-0.18703481171888114f)
#define W5 0.030841381835986965f
#define W6 0.032883011666982945f
#define W7 (-0.010597401784997278f)

namespace {

constexpr int NROW = 2048;     // 32 * 64
constexpr int N    = 8192;
constexpr int L1   = 4099;     // dwt output lengths per level
constexpr int L2   = 2053;
constexpr int L3   = 1030;

// shared memory layout (floats)
constexpr int OFF_A1 = 0;          // 4099   (t1 aliases this region, 2054)
constexpr int OFF_D1 = 4099;       // 4099
constexpr int OFF_A2 = 8198;       // 2053
constexpr int OFF_D2 = 10251;      // 2053
constexpr int OFF_A3 = 12304;      // 1030
constexpr int OFF_D3 = 13334;      // 1030
constexpr int OFF_T2 = 14364;      // 4100
constexpr int SM_FLOATS = 18464;   // 73856 bytes

__device__ __forceinline__ int symq(int q, int m) {
    q = (q < 0) ? (-q - 1) : q;
    return (q >= m) ? (2 * m - 1 - q) : q;
}

// One analysis level: out lengths lenOut = (m+5)/2 + 1.
// cA[o] = sum_j RLO[j] * in[sym(2o + j - 6)], cD with RHI.
__device__ __forceinline__ void dwt_level(const float* __restrict__ in, int m, int lenOut,
                                          float* __restrict__ oa, float* __restrict__ od) {
    constexpr float RLO[8] = { W0,  W1,  W2,  W3,  W4,  W5,  W6,  W7};
    constexpr float RHI[8] = { W7, -W6,  W5, -W4,  W3, -W2,  W1, -W0};
    for (int o = threadIdx.x; o < lenOut; o += blockDim.x) {
        int base = 2 * o - 6;
        float sA = 0.f, sD = 0.f;
        if (base >= 0 && base + 7 < m) {
            #pragma unroll
            for (int j = 0; j < 8; ++j) {
                float v = in[base + j];
                sA = fmaf(v, RLO[j], sA);
                sD = fmaf(v, RHI[j], sD);
            }
        } else {
            #pragma unroll
            for (int j = 0; j < 8; ++j) {
                float v = in[symq(base + j, m)];
                sA = fmaf(v, RLO[j], sA);
                sD = fmaf(v, RHI[j], sD);
            }
        }
        oa[o] = sA;
        od[o] = sD;
    }
}

// One synthesis (idwt) branch with a single non-zero input.
// Output length 2m-6. Pair (2p, 2p+1) both consume in[p..p+3]; no bounds checks needed.
// HI=0 -> DEC_LO branch, HI=1 -> DEC_HI branch.
// out must be 8-byte aligned (pairs stored as float2).
template<int HI>
__device__ __forceinline__ void idwt_one(const float* __restrict__ in, int m,
                                         float* __restrict__ out) {
    const float E0 = HI ?  W1 : W6;
    const float E1 = HI ?  W3 : W4;
    const float E2 = HI ?  W5 : W2;
    const float E3 = HI ?  W7 : W0;
    const float O0 = HI ? -W0 : W7;
    const float O1 = HI ? -W2 : W5;
    const float O2 = HI ? -W4 : W3;
    const float O3 = HI ? -W6 : W1;
    const int np = m - 3;   // number of output pairs
    float2* __restrict__ out2 = reinterpret_cast<float2*>(out);
    for (int p = threadIdx.x; p < np; p += blockDim.x) {
        float v0 = in[p], v1 = in[p + 1], v2 = in[p + 2], v3 = in[p + 3];
        float e = fmaf(v0, E0, fmaf(v1, E1, fmaf(v2, E2, v3 * E3)));
        float o = fmaf(v0, O0, fmaf(v1, O1, fmaf(v2, O2, v3 * O3)));
        out2[p] = make_float2(e, o);
    }
}

__global__ void __launch_bounds__(256, 3)
dwt_bands_kernel(const float* __restrict__ x, float* __restrict__ out) {
    extern __shared__ float sm[];
    float* a1 = sm + OFF_A1;
    float* d1 = sm + OFF_D1;
    float* a2 = sm + OFF_A2;
    float* d2 = sm + OFF_D2;
    float* a3 = sm + OFF_A3;
    float* d3 = sm + OFF_D3;
    float* t2 = sm + OFF_T2;
    float* t1 = sm + OFF_A1;   // alias: a1 dead after level 2

    const int row = blockIdx.x;
    const float* __restrict__ xr = x + (size_t)row * N;

    // ---- analysis cascade ----
    dwt_level(xr, N,  L1, a1, d1);  __syncthreads();
    dwt_level(a1, L1, L2, a2, d2);  __syncthreads();
    dwt_level(a2, L2, L3, a3, d3);  __syncthreads();

    float* ob0 = out + (size_t)row * N;
    float* ob1 = ob0 + (size_t)NROW * N;
    float* ob2 = ob1 + (size_t)NROW * N;
    float* ob3 = ob2 + (size_t)NROW * N;

    // ---- band 0: keep a3 ----
    idwt_one<0>(a3, L3,   t1);   __syncthreads();   // 2054 (trim -> use 2053)
    idwt_one<0>(t1, 2053, t2);   __syncthreads();   // 4100 (trim -> use 4099)
    idwt_one<0>(t2, 4099, ob0);  __syncthreads();   // 8192 -> global

    // ---- band 1: keep d3 ----
    idwt_one<1>(d3, L3,   t1);   __syncthreads();
    idwt_one<0>(t1, 2053, t2);   __syncthreads();
    idwt_one<0>(t2, 4099, ob1);  __syncthreads();

    // ---- band 2: keep d2 ----
    idwt_one<1>(d2, L2,   t2);   __syncthreads();   // 4100 (trim -> 4099)
    idwt_one<0>(t2, 4099, ob2);                     // 8192 -> global

    // ---- band 3: keep d1 ----
    idwt_one<1>(d1, L1,   ob3);                     // 2*4096 = 8192 -> global
}

}  // namespace

extern "C" void kernel_launch(void* const* d_in, const int* in_sizes, int n_in,
                              void* d_out, int out_size) {
    const float* x = (const float*)d_in[0];
    float* out = (float*)d_out;
    constexpr int smem_bytes = SM_FLOATS * (int)sizeof(float);
    cudaFuncSetAttribute(dwt_bands_kernel,
                         cudaFuncAttributeMaxDynamicSharedMemorySize, smem_bytes);
    dwt_bands_kernel<<<NROW, 256, smem_bytes>>>(x, out);
}

// round 2
// speedup vs baseline: 1.2237x; 1.2237x over previous
#include <cuda_runtime.h>

#define W0 0.23037781330885523f
#define W1 0.7148465705525415f
#define W2 0.6308807679295904f
#define W3 (-0.02798376941698385f)
#define W4 (-0.18703481171888114f)
#define W5 0.030841381835986965f
#define W6 0.032883011666982945f
#define W7 (-0.010597401784997278f)

namespace {

constexpr int NROW = 2048;     // 32 * 64
constexpr int N    = 8192;
constexpr int L1   = 4099;     // dwt output lengths per level
constexpr int L2   = 2053;
constexpr int L3   = 1030;

// shared memory layout (floats) -- all offsets multiples of 4 (16B aligned)
constexpr int OFF_A1  = 0;         // 4100   a1 (dead after S2)
constexpr int OFF_D1  = 4100;      // 4100   d1 -> then t2b (band2) -> then t2 (band1)
constexpr int OFF_A2  = 8200;      // 2056   a2 -> then t1a (band0)
constexpr int OFF_D2  = 10256;     // 2056   d2 -> then t1b (band1)
constexpr int OFF_A3  = 12312;     // 1032
constexpr int OFF_D3  = 13344;     // 1032
constexpr int OFF_T2A = 14376;     // 4100   t2 (band0)
constexpr int SM_FLOATS = 18476;   // 73904 bytes

__device__ __forceinline__ int symq(int q, int m) {
    q = (q < 0) ? (-q - 1) : q;
    return (q >= m) ? (2 * m - 1 - q) : q;
}

// One analysis level: lenOut = (m+5)/2 + 1.
// cA[o] = sum_j RLO[j] * in[sym(2o + j - 6)], cD with RHI.
// Interior path: 4x float2 loads (conflict-free LDS.64 / LDG.64).
__device__ __forceinline__ void dwt_level(const float* __restrict__ in, int m, int lenOut,
                                          float* __restrict__ oa, float* __restrict__ od) {
    const float2* __restrict__ in2 = reinterpret_cast<const float2*>(in);
    for (int o = threadIdx.x; o < lenOut; o += blockDim.x) {
        const int base = 2 * o - 6;
        float sA, sD;
        if (base >= 0 && base + 7 < m) {
            float2 p0 = in2[o - 3];
            float2 p1 = in2[o - 2];
            float2 p2 = in2[o - 1];
            float2 p3 = in2[o];
            sA = fmaf(p0.x, W0, fmaf(p0.y, W1, fmaf(p1.x, W2, fmaf(p1.y, W3,
                 fmaf(p2.x, W4, fmaf(p2.y, W5, fmaf(p3.x, W6, p3.y * W7)))))));
            sD = fmaf(p0.x, W7, fmaf(p0.y, -W6, fmaf(p1.x, W5, fmaf(p1.y, -W4,
                 fmaf(p2.x, W3, fmaf(p2.y, -W2, fmaf(p3.x, W1, p3.y * -W0)))))));
        } else {
            const float RLO[8] = { W0,  W1,  W2,  W3,  W4,  W5,  W6,  W7};
            const float RHI[8] = { W7, -W6,  W5, -W4,  W3, -W2,  W1, -W0};
            sA = 0.f; sD = 0.f;
            #pragma unroll
            for (int j = 0; j < 8; ++j) {
                float v = in[symq(base + j, m)];
                sA = fmaf(v, RLO[j], sA);
                sD = fmaf(v, RHI[j], sD);
            }
        }
        oa[o] = sA;
        od[o] = sD;
    }
}

// One synthesis (idwt) branch with single non-zero input, output length 2m-6.
// Vectorized: each thread computes 2 output pairs (one float4 store) from
// 2x LDS.64 + 1x LDS.32. HI=0 -> DEC_LO branch, HI=1 -> DEC_HI branch.
// in must be 8B aligned, out 16B aligned.
template<int HI>
__device__ __forceinline__ void idwt_vec(const float* __restrict__ in, int m,
                                         float* __restrict__ out) {
    const float E0 = HI ?  W1 : W6;
    const float E1 = HI ?  W3 : W4;
    const float E2 = HI ?  W5 : W2;
    const float E3 = HI ?  W7 : W0;
    const float O0 = HI ? -W0 : W7;
    const float O1 = HI ? -W2 : W5;
    const float O2 = HI ? -W4 : W3;
    const float O3 = HI ? -W6 : W1;
    const int np = m - 3;            // output pairs
    const int nq = np >> 1;          // quads (2 pairs each)
    const float2* __restrict__ in2 = reinterpret_cast<const float2*>(in);
    float4* __restrict__ out4 = reinterpret_cast<float4*>(out);
    for (int q = threadIdx.x; q < nq; q += blockDim.x) {
        float2 a = in2[q];
        float2 b = in2[q + 1];
        float  c = in[2 * q + 4];
        float4 r;
        r.x = fmaf(a.x, E0, fmaf(a.y, E1, fmaf(b.x, E2, b.y * E3)));
        r.y = fmaf(a.x, O0, fmaf(a.y, O1, fmaf(b.x, O2, b.y * O3)));
        r.z = fmaf(a.y, E0, fmaf(b.x, E1, fmaf(b.y, E2, c * E3)));
        r.w = fmaf(a.y, O0, fmaf(b.x, O1, fmaf(b.y, O2, c * O3)));
        out4[q] = r;
    }
    if ((np & 1) && threadIdx.x == 0) {   // odd tail pair
        int p = np - 1;
        float v0 = in[p], v1 = in[p + 1], v2 = in[p + 2], v3 = in[p + 3];
        out[2 * p]     = fmaf(v0, E0, fmaf(v1, E1, fmaf(v2, E2, v3 * E3)));
        out[2 * p + 1] = fmaf(v0, O0, fmaf(v1, O1, fmaf(v2, O2, v3 * O3)));
    }
}

__global__ void __launch_bounds__(384, 3)
dwt_bands_kernel(const float* __restrict__ x, float* __restrict__ out) {
    extern __shared__ float sm[];
    float* a1  = sm + OFF_A1;
    float* d1  = sm + OFF_D1;
    float* a2  = sm + OFF_A2;
    float* d2  = sm + OFF_D2;
    float* a3  = sm + OFF_A3;
    float* d3  = sm + OFF_D3;
    float* t2a = sm + OFF_T2A;
    float* t2b = sm + OFF_D1;    // aliases: D1 region reused after d1 dies
    float* t1a = sm + OFF_A2;    // A2 region reused after a2 dies
    float* t1b = sm + OFF_D2;    // D2 region reused after d2 dies

    const int row = blockIdx.x;
    const float* __restrict__ xr = x + (size_t)row * N;
    float* ob0 = out + (size_t)row * N;
    float* ob1 = ob0 + (size_t)NROW * N;
    float* ob2 = ob1 + (size_t)NROW * N;
    float* ob3 = ob2 + (size_t)NROW * N;

    // S1: level-1 analysis (global -> smem)
    dwt_level(xr, N, L1, a1, d1);
    __syncthreads();

    // S2: level-2 analysis  ||  band3 output (only needs d1)
    dwt_level(a1, L1, L2, a2, d2);
    idwt_vec<1>(d1, L1, ob3);                 // 2*4096 = 8192 -> global
    __syncthreads();                          // d1, a1 dead after this

    // S3: level-3 analysis  ||  band2 stage-1 (d2 -> t2b in D1 region)
    dwt_level(a2, L2, L3, a3, d3);
    idwt_vec<1>(d2, L2, t2b);                 // 4100 (use 4099)
    __syncthreads();                          // a2, d2 dead after this

    // S4: band0 t1 (a3)  ||  band1 t1 (d3)  ||  band2 output (t2b)
    idwt_vec<0>(a3, L3, t1a);                 // 2054 (use 2053)
    idwt_vec<1>(d3, L3, t1b);                 // 2054 (use 2053)
    idwt_vec<0>(t2b, 4099, ob2);              // 8192 -> global
    __syncthreads();                          // t2b (D1) free again

    // S5: band0 t2  ||  band1 t2 (into D1 region)
    idwt_vec<0>(t1a, 2053, t2a);              // 4100 (use 4099)
    idwt_vec<0>(t1b, 2053, t2b);              // 4100 (use 4099)
    __syncthreads();

    // S6: band0 & band1 outputs
    idwt_vec<0>(t2a, 4099, ob0);              // 8192 -> global
    idwt_vec<0>(t2b, 4099, ob1);              // 8192 -> global
}

}  // namespace

extern "C" void kernel_launch(void* const* d_in, const int* in_sizes, int n_in,
                              void* d_out, int out_size) {
    const float* x = (const float*)d_in[0];
    float* out = (float*)d_out;
    constexpr int smem_bytes = SM_FLOATS * (int)sizeof(float);
    cudaFuncSetAttribute(dwt_bands_kernel,
                         cudaFuncAttributeMaxDynamicSharedMemorySize, smem_bytes);
    dwt_bands_kernel<<<NROW, 384, smem_bytes>>>(x, out);
}

// round 3
// speedup vs baseline: 1.3724x; 1.1215x over previous
#include <cuda_runtime.h>

#define W0 0.23037781330885523f
#define W1 0.7148465705525415f
#define W2 0.6308807679295904f
#define W3 (-0.02798376941698385f)
#define W4 (-0.18703481171888114f)
#define W5 0.030841381835986965f
#define W6 0.032883011666982945f
#define W7 (-0.010597401784997278f)

namespace {

constexpr int NROW = 2048;     // 32 * 64
constexpr int N    = 8192;
constexpr int L1   = 4099;     // dwt output lengths per level
constexpr int L2   = 2053;
constexpr int L3   = 1030;

// shared memory layout (floats) -- all offsets multiples of 4 (16B aligned)
// Regions are reused across stages once their first tenant dies:
//   A1: a1 (S1-S2)      -> t2a (S5-S6)
//   D1: d1 (S1-S2)      -> t2b band2 (S3-S4) -> t2b band1 (S5-S6)
//   A2: a2 (S2-S3)      -> t1a (S4-S5)
//   D2: d2 (S2-S3)      -> t1b (S4-S5)
constexpr int OFF_A1 = 0;          // 4100
constexpr int OFF_D1 = 4100;       // 4100
constexpr int OFF_A2 = 8200;       // 2056
constexpr int OFF_D2 = 10256;      // 2056
constexpr int OFF_A3 = 12312;      // 1032
constexpr int OFF_D3 = 13344;      // 1032
constexpr int SM_FLOATS = 14376;   // 57504 bytes -> 4 CTAs/SM

__device__ __forceinline__ int symq(int q, int m) {
    q = (q < 0) ? (-q - 1) : q;
    return (q >= m) ? (2 * m - 1 - q) : q;
}

// Scalar (boundary) analysis for one output index o.
__device__ __forceinline__ void dwt_scalar(const float* __restrict__ in, int m, int o,
                                           float& sA, float& sD) {
    const float RLO[8] = { W0,  W1,  W2,  W3,  W4,  W5,  W6,  W7};
    const float RHI[8] = { W7, -W6,  W5, -W4,  W3, -W2,  W1, -W0};
    const int base = 2 * o - 6;
    sA = 0.f; sD = 0.f;
    #pragma unroll
    for (int j = 0; j < 8; ++j) {
        float v = in[symq(base + j, m)];
        sA = fmaf(v, RLO[j], sA);
        sD = fmaf(v, RHI[j], sD);
    }
}

// One analysis level: lenOut = (m+5)/2 + 1.
// Pair-per-thread: outputs (2t, 2t+1) from floats in[4t-6 .. 4t+3],
// loaded as 3x float4 (16B lane stride -> contiguous, conflict-free).
// in, oa, od must be 16B aligned.
__device__ __forceinline__ void dwt_level(const float* __restrict__ in, int m, int lenOut,
                                          float* __restrict__ oa, float* __restrict__ od) {
    const float4* __restrict__ in4 = reinterpret_cast<const float4*>(in);
    float2* __restrict__ oa2 = reinterpret_cast<float2*>(oa);
    float2* __restrict__ od2 = reinterpret_cast<float2*>(od);
    const int np = lenOut >> 1;
    for (int t = threadIdx.x; t < np; t += blockDim.x) {
        const int base = 4 * t - 6;
        float a0, d0, a1, d1;
        if (base >= 0 && base + 9 < m) {
            float4 q0 = in4[t - 2];   // .z=v0 .w=v1
            float4 q1 = in4[t - 1];   // v2..v5
            float4 q2 = in4[t];       // v6..v9
            a0 = fmaf(q0.z, W0, fmaf(q0.w, W1, fmaf(q1.x, W2, fmaf(q1.y, W3,
                 fmaf(q1.z, W4, fmaf(q1.w, W5, fmaf(q2.x, W6, q2.y * W7)))))));
            d0 = fmaf(q0.z, W7, fmaf(q0.w, -W6, fmaf(q1.x, W5, fmaf(q1.y, -W4,
                 fmaf(q1.z, W3, fmaf(q1.w, -W2, fmaf(q2.x, W1, q2.y * -W0)))))));
            a1 = fmaf(q1.x, W0, fmaf(q1.y, W1, fmaf(q1.z, W2, fmaf(q1.w, W3,
                 fmaf(q2.x, W4, fmaf(q2.y, W5, fmaf(q2.z, W6, q2.w * W7)))))));
            d1 = fmaf(q1.x, W7, fmaf(q1.y, -W6, fmaf(q1.z, W5, fmaf(q1.w, -W4,
                 fmaf(q2.x, W3, fmaf(q2.y, -W2, fmaf(q2.z, W1, q2.w * -W0)))))));
        } else {
            dwt_scalar(in, m, 2 * t,     a0, d0);
            dwt_scalar(in, m, 2 * t + 1, a1, d1);
        }
        oa2[t] = make_float2(a0, a1);
        od2[t] = make_float2(d0, d1);
    }
    if ((lenOut & 1) && threadIdx.x == 0) {   // odd tail output
        float a, d;
        dwt_scalar(in, m, lenOut - 1, a, d);
        oa[lenOut - 1] = a;
        od[lenOut - 1] = d;
    }
}

// One synthesis (idwt) branch with single non-zero input, output length 2m-6.
// Each thread computes 2 output pairs (one float4 store) from 2x LDS.64 + 1x LDS.32.
// HI=0 -> DEC_LO branch, HI=1 -> DEC_HI branch. in 8B aligned, out 16B aligned.
template<int HI>
__device__ __forceinline__ void idwt_vec(const float* __restrict__ in, int m,
                                         float* __restrict__ out) {
    const float E0 = HI ?  W1 : W6;
    const float E1 = HI ?  W3 : W4;
    const float E2 = HI ?  W5 : W2;
    const float E3 = HI ?  W7 : W0;
    const float O0 = HI ? -W0 : W7;
    const float O1 = HI ? -W2 : W5;
    const float O2 = HI ? -W4 : W3;
    const float O3 = HI ? -W6 : W1;
    const int np = m - 3;            // output pairs
    const int nq = np >> 1;          // quads (2 pairs each)
    const float2* __restrict__ in2 = reinterpret_cast<const float2*>(in);
    float4* __restrict__ out4 = reinterpret_cast<float4*>(out);
    for (int q = threadIdx.x; q < nq; q += blockDim.x) {
        float2 a = in2[q];
        float2 b = in2[q + 1];
        float  c = in[2 * q + 4];
        float4 r;
        r.x = fmaf(a.x, E0, fmaf(a.y, E1, fmaf(b.x, E2, b.y * E3)));
        r.y = fmaf(a.x, O0, fmaf(a.y, O1, fmaf(b.x, O2, b.y * O3)));
        r.z = fmaf(a.y, E0, fmaf(b.x, E1, fmaf(b.y, E2, c * E3)));
        r.w = fmaf(a.y, O0, fmaf(b.x, O1, fmaf(b.y, O2, c * O3)));
        out4[q] = r;
    }
    if ((np & 1) && threadIdx.x == 0) {   // odd tail pair
        int p = np - 1;
        float v0 = in[p], v1 = in[p + 1], v2 = in[p + 2], v3 = in[p + 3];
        out[2 * p]     = fmaf(v0, E0, fmaf(v1, E1, fmaf(v2, E2, v3 * E3)));
        out[2 * p + 1] = fmaf(v0, O0, fmaf(v1, O1, fmaf(v2, O2, v3 * O3)));
    }
}

__global__ void __launch_bounds__(384, 4)
dwt_bands_kernel(const float* __restrict__ x, float* __restrict__ out) {
    extern __shared__ float sm[];
    float* a1  = sm + OFF_A1;
    float* d1  = sm + OFF_D1;
    float* a2  = sm + OFF_A2;
    float* d2  = sm + OFF_D2;
    float* a3  = sm + OFF_A3;
    float* d3  = sm + OFF_D3;
    float* t2a = sm + OFF_A1;    // alias: A1 dead after S2
    float* t2b = sm + OFF_D1;    // alias: D1 dead after S2
    float* t1a = sm + OFF_A2;    // alias: A2 dead after S3
    float* t1b = sm + OFF_D2;    // alias: D2 dead after S3

    const int row = blockIdx.x;
    const float* __restrict__ xr = x + (size_t)row * N;
    float* ob0 = out + (size_t)row * N;
    float* ob1 = ob0 + (size_t)NROW * N;
    float* ob2 = ob1 + (size_t)NROW * N;
    float* ob3 = ob2 + (size_t)NROW * N;

    // S1: level-1 analysis (global -> smem)
    dwt_level(xr, N, L1, a1, d1);
    __syncthreads();

    // S2: level-2 analysis  ||  band3 output (only needs d1)
    dwt_level(a1, L1, L2, a2, d2);
    idwt_vec<1>(d1, L1, ob3);                 // 2*4096 = 8192 -> global
    __syncthreads();                          // a1, d1 dead

    // S3: level-3 analysis  ||  band2 stage-1 (d2 -> t2b in D1 region)
    dwt_level(a2, L2, L3, a3, d3);
    idwt_vec<1>(d2, L2, t2b);                 // 4100 (use 4099)
    __syncthreads();                          // a2, d2 dead

    // S4: band0 t1 (a3)  ||  band1 t1 (d3)  ||  band2 output (t2b)
    idwt_vec<0>(a3, L3, t1a);                 // 2054 (use 2053)
    idwt_vec<1>(d3, L3, t1b);                 // 2054 (use 2053)
    idwt_vec<0>(t2b, 4099, ob2);              // 8192 -> global
    __syncthreads();                          // t2b (D1) free, a3/d3 dead

    // S5: band0 t2 (into A1 region)  ||  band1 t2 (into D1 region)
    idwt_vec<0>(t1a, 2053, t2a);              // 4100 (use 4099)
    idwt_vec<0>(t1b, 2053, t2b);              // 4100 (use 4099)
    __syncthreads();

    // S6: band0 & band1 outputs
    idwt_vec<0>(t2a, 4099, ob0);              // 8192 -> global
    idwt_vec<0>(t2b, 4099, ob1);              // 8192 -> global
}

}  // namespace

extern "C" void kernel_launch(void* const* d_in, const int* in_sizes, int n_in,
                              void* d_out, int out_size) {
    const float* x = (const float*)d_in[0];
    float* out = (float*)d_out;
    constexpr int smem_bytes = SM_FLOATS * (int)sizeof(float);
    cudaFuncSetAttribute(dwt_bands_kernel,
                         cudaFuncAttributeMaxDynamicSharedMemorySize, smem_bytes);
    dwt_bands_kernel<<<NROW, 384, smem_bytes>>>(x, out);
}

// round 4
// speedup vs baseline: 1.4474x; 1.0547x over previous
#include <cuda_runtime.h>

#define W0 0.23037781330885523f
#define W1 0.7148465705525415f
#define W2 0.6308807679295904f
#define W3 (-0.02798376941698385f)
#define W4 (-0.18703481171888114f)
#define W5 0.030841381835986965f
#define W6 0.032883011666982945f
#define W7 (-0.010597401784997278f)

namespace {

constexpr int NROW = 2048;     // 32 * 64
constexpr int N    = 8192;
constexpr int L1   = 4099;     // dwt output lengths per level
constexpr int L2   = 2053;
constexpr int L3   = 1030;

// shared memory layout (floats) -- all offsets multiples of 4 (16B aligned)
// Region lifetimes (S = stage between barriers):
//   A1 region (4100): a1 (S1-S2) -> a3 [0,1030) + d3 [1032,2062) (S3-S4) -> t2a (S5-S6)
//   D1 region (4100): d1 (S1-S2) -> t2b band2 (S3-S4) -> t2b band1 (S5-S6)
//   A2 region (2056): a2 (S2-S3) -> t1a (S4-S5)
//   D2 region (2056): d2 (S2-S3) -> t1b (S4-S5)
constexpr int OFF_A1 = 0;          // 4100
constexpr int OFF_D1 = 4100;       // 4100
constexpr int OFF_A2 = 8200;       // 2056
constexpr int OFF_D2 = 10256;      // 2056
constexpr int OFF_A3 = OFF_A1;         // 1030, inside dead A1
constexpr int OFF_D3 = OFF_A1 + 1032;  // 1030, inside dead A1
constexpr int SM_FLOATS = 12312;   // 49248 bytes; 4 x (49248+1024) = 201KB < 228KB -> 4 CTAs/SM

__device__ __forceinline__ int symq(int q, int m) {
    q = (q < 0) ? (-q - 1) : q;
    return (q >= m) ? (2 * m - 1 - q) : q;
}

// Scalar (boundary) analysis for one output index o.
__device__ __forceinline__ void dwt_scalar(const float* __restrict__ in, int m, int o,
                                           float& sA, float& sD) {
    const float RLO[8] = { W0,  W1,  W2,  W3,  W4,  W5,  W6,  W7};
    const float RHI[8] = { W7, -W6,  W5, -W4,  W3, -W2,  W1, -W0};
    const int base = 2 * o - 6;
    sA = 0.f; sD = 0.f;
    #pragma unroll
    for (int j = 0; j < 8; ++j) {
        float v = in[symq(base + j, m)];
        sA = fmaf(v, RLO[j], sA);
        sD = fmaf(v, RHI[j], sD);
    }
}

// One analysis level: lenOut = (m+5)/2 + 1.
// Pair-per-thread: outputs (2t, 2t+1) from floats in[4t-6 .. 4t+3],
// loaded as 3x float4 (16B lane stride -> contiguous, conflict-free).
// in, oa, od must be 16B aligned.
__device__ __forceinline__ void dwt_level(const float* __restrict__ in, int m, int lenOut,
                                          float* __restrict__ oa, float* __restrict__ od) {
    const float4* __restrict__ in4 = reinterpret_cast<const float4*>(in);
    float2* __restrict__ oa2 = reinterpret_cast<float2*>(oa);
    float2* __restrict__ od2 = reinterpret_cast<float2*>(od);
    const int np = lenOut >> 1;
    for (int t = threadIdx.x; t < np; t += blockDim.x) {
        const int base = 4 * t - 6;
        float a0, d0, a1, d1;
        if (base >= 0 && base + 9 < m) {
            float4 q0 = in4[t - 2];   // .z=v0 .w=v1
            float4 q1 = in4[t - 1];   // v2..v5
            float4 q2 = in4[t];       // v6..v9
            a0 = fmaf(q0.z, W0, fmaf(q0.w, W1, fmaf(q1.x, W2, fmaf(q1.y, W3,
                 fmaf(q1.z, W4, fmaf(q1.w, W5, fmaf(q2.x, W6, q2.y * W7)))))));
            d0 = fmaf(q0.z, W7, fmaf(q0.w, -W6, fmaf(q1.x, W5, fmaf(q1.y, -W4,
                 fmaf(q1.z, W3, fmaf(q1.w, -W2, fmaf(q2.x, W1, q2.y * -W0)))))));
            a1 = fmaf(q1.x, W0, fmaf(q1.y, W1, fmaf(q1.z, W2, fmaf(q1.w, W3,
                 fmaf(q2.x, W4, fmaf(q2.y, W5, fmaf(q2.z, W6, q2.w * W7)))))));
            d1 = fmaf(q1.x, W7, fmaf(q1.y, -W6, fmaf(q1.z, W5, fmaf(q1.w, -W4,
                 fmaf(q2.x, W3, fmaf(q2.y, -W2, fmaf(q2.z, W1, q2.w * -W0)))))));
        } else {
            dwt_scalar(in, m, 2 * t,     a0, d0);
            dwt_scalar(in, m, 2 * t + 1, a1, d1);
        }
        oa2[t] = make_float2(a0, a1);
        od2[t] = make_float2(d0, d1);
    }
    if ((lenOut & 1) && threadIdx.x == 0) {   // odd tail output
        float a, d;
        dwt_scalar(in, m, lenOut - 1, a, d);
        oa[lenOut - 1] = a;
        od[lenOut - 1] = d;
    }
}

// One synthesis (idwt) branch with single non-zero input, output length 2m-6.
// Each thread computes 2 output pairs (one float4 store) from 2x LDS.64 + 1x LDS.32.
// HI=0 -> DEC_LO branch, HI=1 -> DEC_HI branch. in 8B aligned, out 16B aligned.
template<int HI>
__device__ __forceinline__ void idwt_vec(const float* __restrict__ in, int m,
                                         float* __restrict__ out) {
    const float E0 = HI ?  W1 : W6;
    const float E1 = HI ?  W3 : W4;
    const float E2 = HI ?  W5 : W2;
    const float E3 = HI ?  W7 : W0;
    const float O0 = HI ? -W0 : W7;
    const float O1 = HI ? -W2 : W5;
    const float O2 = HI ? -W4 : W3;
    const float O3 = HI ? -W6 : W1;
    const int np = m - 3;            // output pairs
    const int nq = np >> 1;          // quads (2 pairs each)
    const float2* __restrict__ in2 = reinterpret_cast<const float2*>(in);
    float4* __restrict__ out4 = reinterpret_cast<float4*>(out);
    for (int q = threadIdx.x; q < nq; q += blockDim.x) {
        float2 a = in2[q];
        float2 b = in2[q + 1];
        float  c = in[2 * q + 4];
        float4 r;
        r.x = fmaf(a.x, E0, fmaf(a.y, E1, fmaf(b.x, E2, b.y * E3)));
        r.y = fmaf(a.x, O0, fmaf(a.y, O1, fmaf(b.x, O2, b.y * O3)));
        r.z = fmaf(a.y, E0, fmaf(b.x, E1, fmaf(b.y, E2, c * E3)));
        r.w = fmaf(a.y, O0, fmaf(b.x, O1, fmaf(b.y, O2, c * O3)));
        out4[q] = r;
    }
    if ((np & 1) && threadIdx.x == 0) {   // odd tail pair
        int p = np - 1;
        float v0 = in[p], v1 = in[p + 1], v2 = in[p + 2], v3 = in[p + 3];
        out[2 * p]     = fmaf(v0, E0, fmaf(v1, E1, fmaf(v2, E2, v3 * E3)));
        out[2 * p + 1] = fmaf(v0, O0, fmaf(v1, O1, fmaf(v2, O2, v3 * O3)));
    }
}

__global__ void __launch_bounds__(384, 4)
dwt_bands_kernel(const float* __restrict__ x, float* __restrict__ out) {
    extern __shared__ float sm[];
    float* a1  = sm + OFF_A1;
    float* d1  = sm + OFF_D1;
    float* a2  = sm + OFF_A2;
    float* d2  = sm + OFF_D2;
    float* a3  = sm + OFF_A3;    // inside dead A1 region (S3-S4)
    float* d3  = sm + OFF_D3;    // inside dead A1 region (S3-S4)
    float* t2a = sm + OFF_A1;    // A1 region, after a3/d3 die (S5-S6)
    float* t2b = sm + OFF_D1;    // D1 region, after d1 dies
    float* t1a = sm + OFF_A2;    // A2 region, after a2 dies
    float* t1b = sm + OFF_D2;    // D2 region, after d2 dies

    const int row = blockIdx.x;
    const float* __restrict__ xr = x + (size_t)row * N;
    float* ob0 = out + (size_t)row * N;
    float* ob1 = ob0 + (size_t)NROW * N;
    float* ob2 = ob1 + (size_t)NROW * N;
    float* ob3 = ob2 + (size_t)NROW * N;

    // S1: level-1 analysis (global -> smem)
    dwt_level(xr, N, L1, a1, d1);
    __syncthreads();

    // S2: level-2 analysis  ||  band3 output (only needs d1)
    dwt_level(a1, L1, L2, a2, d2);
    idwt_vec<1>(d1, L1, ob3);                 // 2*4096 = 8192 -> global
    __syncthreads();                          // a1, d1 dead

    // S3: level-3 analysis (a3/d3 into dead A1)  ||  band2 stage-1 (d2 -> t2b)
    dwt_level(a2, L2, L3, a3, d3);
    idwt_vec<1>(d2, L2, t2b);                 // 4100 (use 4099)
    __syncthreads();                          // a2, d2 dead

    // S4: band0 t1 (a3)  ||  band1 t1 (d3)  ||  band2 output (t2b)
    idwt_vec<0>(a3, L3, t1a);                 // 2054 (use 2053)
    idwt_vec<1>(d3, L3, t1b);                 // 2054 (use 2053)
    idwt_vec<0>(t2b, 4099, ob2);              // 8192 -> global
    __syncthreads();                          // a3, d3 dead; D1 free

    // S5: band0 t2 (A1 region)  ||  band1 t2 (D1 region)
    idwt_vec<0>(t1a, 2053, t2a);              // 4100 (use 4099)
    idwt_vec<0>(t1b, 2053, t2b);              // 4100 (use 4099)
    __syncthreads();

    // S6: band0 & band1 outputs
    idwt_vec<0>(t2a, 4099, ob0);              // 8192 -> global
    idwt_vec<0>(t2b, 4099, ob1);              // 8192 -> global
}

}  // namespace

extern "C" void kernel_launch(void* const* d_in, const int* in_sizes, int n_in,
                              void* d_out, int out_size) {
    const float* x = (const float*)d_in[0];
    float* out = (float*)d_out;
    constexpr int smem_bytes = SM_FLOATS * (int)sizeof(float);
    cudaFuncSetAttribute(dwt_bands_kernel,
                         cudaFuncAttributeMaxDynamicSharedMemorySize, smem_bytes);
    dwt_bands_kernel<<<NROW, 384, smem_bytes>>>(x, out);
}

// round 5
// speedup vs baseline: 1.5356x; 1.0609x over previous
#include <cuda_runtime.h>

#define W0 0.23037781330885523f
#define W1 0.7148465705525415f
#define W2 0.6308807679295904f
#define W3 (-0.02798376941698385f)
#define W4 (-0.18703481171888114f)
#define W5 0.030841381835986965f
#define W6 0.032883011666982945f
#define W7 (-0.010597401784997278f)

namespace {

constexpr int NROW = 2048;     // 32 * 64
constexpr int N    = 8192;
constexpr int L1   = 4099;     // dwt output lengths per level
constexpr int L2   = 2053;
constexpr int L3   = 1030;

// shared memory layout (floats) -- all offsets multiples of 4 (16B aligned)
// Region lifetimes:
//   A1 (4100): a1 (S1-S2) -> a3 [0,1030) + d3 [1032,2062) (S3-S4)
//   D1 (4100): d1 (S1-S2)
//   A2 (2056): a2 (S2-S3) -> t1a (S4-S5)
//   D2 (2056): d2 (S2-S3) -> t1b (S4-S5)
constexpr int OFF_A1 = 0;          // 4100
constexpr int OFF_D1 = 4100;       // 4100
constexpr int OFF_A2 = 8200;       // 2056
constexpr int OFF_D2 = 10256;      // 2056
constexpr int OFF_A3 = OFF_A1;         // 1030, inside dead A1
constexpr int OFF_D3 = OFF_A1 + 1032;  // 1030, inside dead A1
constexpr int SM_FLOATS = 12312;   // 49248 B; 4 x (49248+1024) = 201KB < 228KB -> 4 CTAs/SM

__device__ __forceinline__ int symq(int q, int m) {
    q = (q < 0) ? (-q - 1) : q;
    return (q >= m) ? (2 * m - 1 - q) : q;
}

// Scalar (boundary) analysis for one output index o.
__device__ __forceinline__ void dwt_scalar(const float* __restrict__ in, int m, int o,
                                           float& sA, float& sD) {
    const float RLO[8] = { W0,  W1,  W2,  W3,  W4,  W5,  W6,  W7};
    const float RHI[8] = { W7, -W6,  W5, -W4,  W3, -W2,  W1, -W0};
    const int base = 2 * o - 6;
    sA = 0.f; sD = 0.f;
    #pragma unroll
    for (int j = 0; j < 8; ++j) {
        float v = in[symq(base + j, m)];
        sA = fmaf(v, RLO[j], sA);
        sD = fmaf(v, RHI[j], sD);
    }
}

// One analysis level: lenOut = (m+5)/2 + 1. Pair-per-thread via 3x float4 loads.
__device__ __forceinline__ void dwt_level(const float* __restrict__ in, int m, int lenOut,
                                          float* __restrict__ oa, float* __restrict__ od) {
    const float4* __restrict__ in4 = reinterpret_cast<const float4*>(in);
    float2* __restrict__ oa2 = reinterpret_cast<float2*>(oa);
    float2* __restrict__ od2 = reinterpret_cast<float2*>(od);
    const int np = lenOut >> 1;
    for (int t = threadIdx.x; t < np; t += blockDim.x) {
        const int base = 4 * t - 6;
        float a0, d0, a1, d1;
        if (base >= 0 && base + 9 < m) {
            float4 q0 = in4[t - 2];   // .z=v0 .w=v1
            float4 q1 = in4[t - 1];   // v2..v5
            float4 q2 = in4[t];       // v6..v9
            a0 = fmaf(q0.z, W0, fmaf(q0.w, W1, fmaf(q1.x, W2, fmaf(q1.y, W3,
                 fmaf(q1.z, W4, fmaf(q1.w, W5, fmaf(q2.x, W6, q2.y * W7)))))));
            d0 = fmaf(q0.z, W7, fmaf(q0.w, -W6, fmaf(q1.x, W5, fmaf(q1.y, -W4,
                 fmaf(q1.z, W3, fmaf(q1.w, -W2, fmaf(q2.x, W1, q2.y * -W0)))))));
            a1 = fmaf(q1.x, W0, fmaf(q1.y, W1, fmaf(q1.z, W2, fmaf(q1.w, W3,
                 fmaf(q2.x, W4, fmaf(q2.y, W5, fmaf(q2.z, W6, q2.w * W7)))))));
            d1 = fmaf(q1.x, W7, fmaf(q1.y, -W6, fmaf(q1.z, W5, fmaf(q1.w, -W4,
                 fmaf(q2.x, W3, fmaf(q2.y, -W2, fmaf(q2.z, W1, q2.w * -W0)))))));
        } else {
            dwt_scalar(in, m, 2 * t,     a0, d0);
            dwt_scalar(in, m, 2 * t + 1, a1, d1);
        }
        oa2[t] = make_float2(a0, a1);
        od2[t] = make_float2(d0, d1);
    }
    if ((lenOut & 1) && threadIdx.x == 0) {   // odd tail output
        float a, d;
        dwt_scalar(in, m, lenOut - 1, a, d);
        oa[lenOut - 1] = a;
        od[lenOut - 1] = d;
    }
}

// Single synthesis level (used where only one level remains, or to produce t1).
// Output length 2m-6. HI=0 -> DEC_LO, HI=1 -> DEC_HI.
template<int HI>
__device__ __forceinline__ void idwt_vec(const float* __restrict__ in, int m,
                                         float* __restrict__ out) {
    const float E0 = HI ?  W1 : W6;
    const float E1 = HI ?  W3 : W4;
    const float E2 = HI ?  W5 : W2;
    const float E3 = HI ?  W7 : W0;
    const float O0 = HI ? -W0 : W7;
    const float O1 = HI ? -W2 : W5;
    const float O2 = HI ? -W4 : W3;
    const float O3 = HI ? -W6 : W1;
    const int np = m - 3;
    const int nq = np >> 1;
    const float2* __restrict__ in2 = reinterpret_cast<const float2*>(in);
    float4* __restrict__ out4 = reinterpret_cast<float4*>(out);
    for (int q = threadIdx.x; q < nq; q += blockDim.x) {
        float2 a = in2[q];
        float2 b = in2[q + 1];
        float  c = in[2 * q + 4];
        float4 r;
        r.x = fmaf(a.x, E0, fmaf(a.y, E1, fmaf(b.x, E2, b.y * E3)));
        r.y = fmaf(a.x, O0, fmaf(a.y, O1, fmaf(b.x, O2, b.y * O3)));
        r.z = fmaf(a.y, E0, fmaf(b.x, E1, fmaf(b.y, E2, c * E3)));
        r.w = fmaf(a.y, O0, fmaf(b.x, O1, fmaf(b.y, O2, c * O3)));
        out4[q] = r;
    }
    if ((np & 1) && threadIdx.x == 0) {
        int p = np - 1;
        float v0 = in[p], v1 = in[p + 1], v2 = in[p + 2], v3 = in[p + 3];
        out[2 * p]     = fmaf(v0, E0, fmaf(v1, E1, fmaf(v2, E2, v3 * E3)));
        out[2 * p + 1] = fmaf(v0, O0, fmaf(v1, O1, fmaf(v2, O2, v3 * O3)));
    }
}

// Fused TWO synthesis levels: stage A (HIA filter) then stage B (LO filter),
// composed into a single upsample-by-4 convolution. Input length 2053 (trimmed),
// exactly 2048 output groups of 4 (= 8192 samples). Reads in[r .. r+5].
// Equivalent to: t2 = idwt_A(in)[trim to 4099]; out = idwt_LO(t2)  (8192 samples).
template<int HIA>
__device__ __forceinline__ void idwt2_fused(const float* __restrict__ in,
                                            float* __restrict__ out) {
    // stage A filter taps
    const float EA0 = HIA ?  W1 : W6, EA1 = HIA ?  W3 : W4;
    const float EA2 = HIA ?  W5 : W2, EA3 = HIA ?  W7 : W0;
    const float OA0 = HIA ? -W0 : W7, OA1 = HIA ? -W2 : W5;
    const float OA2 = HIA ? -W4 : W3, OA3 = HIA ? -W6 : W1;
    // stage B (LO) taps
    const float EB0 = W6, EB1 = W4, EB2 = W2, EB3 = W0;
    const float OB0 = W7, OB1 = W5, OB2 = W3, OB3 = W1;
    // composed phase coefficients (constant-folded)
    const float C00 = EB0*EA0 + EB1*OA0;
    const float C01 = EB0*EA1 + EB1*OA1 + EB2*EA0 + EB3*OA0;
    const float C02 = EB0*EA2 + EB1*OA2 + EB2*EA1 + EB3*OA1;
    const float C03 = EB0*EA3 + EB1*OA3 + EB2*EA2 + EB3*OA2;
    const float C04 =                     EB2*EA3 + EB3*OA3;
    const float C10 = OB0*EA0 + OB1*OA0;
    const float C11 = OB0*EA1 + OB1*OA1 + OB2*EA0 + OB3*OA0;
    const float C12 = OB0*EA2 + OB1*OA2 + OB2*EA1 + OB3*OA1;
    const float C13 = OB0*EA3 + OB1*OA3 + OB2*EA2 + OB3*OA2;
    const float C14 =                     OB2*EA3 + OB3*OA3;
    const float C20 = EB0*OA0;
    const float C21 = EB0*OA1 + EB1*EA0 + EB2*OA0;
    const float C22 = EB0*OA2 + EB1*EA1 + EB2*OA1 + EB3*EA0;
    const float C23 = EB0*OA3 + EB1*EA2 + EB2*OA2 + EB3*EA1;
    const float C24 =           EB1*EA3 + EB2*OA3 + EB3*EA2;
    const float C25 =                                EB3*EA3;
    const float C30 = OB0*OA0;
    const float C31 = OB0*OA1 + OB1*EA0 + OB2*OA0;
    const float C32 = OB0*OA2 + OB1*EA1 + OB2*OA1 + OB3*EA0;
    const float C33 = OB0*OA3 + OB1*EA2 + OB2*OA2 + OB3*EA1;
    const float C34 =           OB1*EA3 + OB2*OA3 + OB3*EA2;
    const float C35 =                                OB3*EA3;

    float4* __restrict__ out4 = reinterpret_cast<float4*>(out);
    const int ng = N / 4;   // 2048 groups; reads in[r..r+5], r_max+5 = 2052
    for (int r = threadIdx.x; r < ng; r += blockDim.x) {
        float v0 = in[r],     v1 = in[r + 1], v2 = in[r + 2];
        float v3 = in[r + 3], v4 = in[r + 4], v5 = in[r + 5];
        float4 o;
        o.x = fmaf(v0, C00, fmaf(v1, C01, fmaf(v2, C02, fmaf(v3, C03, v4 * C04))));
        o.y = fmaf(v0, C10, fmaf(v1, C11, fmaf(v2, C12, fmaf(v3, C13, v4 * C14))));
        o.z = fmaf(v0, C20, fmaf(v1, C21, fmaf(v2, C22,
              fmaf(v3, C23, fmaf(v4, C24, v5 * C25)))));
        o.w = fmaf(v0, C30, fmaf(v1, C31, fmaf(v2, C32,
              fmaf(v3, C33, fmaf(v4, C34, v5 * C35)))));
        out4[r] = o;
    }
}

__global__ void __launch_bounds__(384, 4)
dwt_bands_kernel(const float* __restrict__ x, float* __restrict__ out) {
    extern __shared__ float sm[];
    float* a1  = sm + OFF_A1;
    float* d1  = sm + OFF_D1;
    float* a2  = sm + OFF_A2;
    float* d2  = sm + OFF_D2;
    float* a3  = sm + OFF_A3;    // inside dead A1 region (S3-S4)
    float* d3  = sm + OFF_D3;    // inside dead A1 region (S3-S4)
    float* t1a = sm + OFF_A2;    // A2 region, after a2 dies
    float* t1b = sm + OFF_D2;    // D2 region, after d2 dies

    const int row = blockIdx.x;
    const float* __restrict__ xr = x + (size_t)row * N;
    float* ob0 = out + (size_t)row * N;
    float* ob1 = ob0 + (size_t)NROW * N;
    float* ob2 = ob1 + (size_t)NROW * N;
    float* ob3 = ob2 + (size_t)NROW * N;

    // S1: level-1 analysis (global -> smem)
    dwt_level(xr, N, L1, a1, d1);
    __syncthreads();

    // S2: level-2 analysis  ||  band3 output (single synthesis level from d1)
    dwt_level(a1, L1, L2, a2, d2);
    idwt_vec<1>(d1, L1, ob3);                 // 2*4096 = 8192 -> global
    __syncthreads();                          // a1, d1 dead

    // S3: level-3 analysis (a3/d3 into dead A1)  ||  band2 fused (d2 -> ob2)
    dwt_level(a2, L2, L3, a3, d3);
    idwt2_fused<1>(d2, ob2);                  // HI then LO, 8192 -> global
    __syncthreads();                          // a2, d2 dead

    // S4: band0 t1 (a3)  ||  band1 t1 (d3)
    idwt_vec<0>(a3, L3, t1a);                 // 2054 (use 2053)
    idwt_vec<1>(d3, L3, t1b);                 // 2054 (use 2053)
    __syncthreads();

    // S5: band0 & band1 fused outputs (LO then LO)
    idwt2_fused<0>(t1a, ob0);                 // 8192 -> global
    idwt2_fused<0>(t1b, ob1);                 // 8192 -> global
}

}  // namespace

extern "C" void kernel_launch(void* const* d_in, const int* in_sizes, int n_in,
                              void* d_out, int out_size) {
    const float* x = (const float*)d_in[0];
    float* out = (float*)d_out;
    constexpr int smem_bytes = SM_FLOATS * (int)sizeof(float);
    cudaFuncSetAttribute(dwt_bands_kernel,
                         cudaFuncAttributeMaxDynamicSharedMemorySize, smem_bytes);
    dwt_bands_kernel<<<NROW, 384, smem_bytes>>>(x, out);
}